// round 1
// baseline (speedup 1.0000x reference)
#include <cuda_runtime.h>

#define BB 16
#define NN 64
#define CC 32
#define NLVL 4
#define NB 60
#define NPAIR (BB*NN*NN)   // 65536

// ---------------- device scratch (static; no allocs) ----------------
__device__ float g_a[2][BB*NN*CC];            // ping-pong scalar reps
__device__ float g_rep[4][BB*NN*7*CC];        // [l][atom][m][c]
__device__ float g_edge[4][NPAIR*CC];         // [l][pair][c]   (33.5 MB)
__device__ float g_cut[NPAIR];
__device__ float g_sph[NPAIR*16];             // 1+3+5+7 packed per pair
__device__ float g_basis[NPAIR*NB];
__device__ float g_part[BB*NN];               // per-atom partial output

// ---------------- geometry: cutoff, sph, gaussian basis ----------------
__global__ void k_geom(const float* __restrict__ pos) {
    int t = blockIdx.x*256 + threadIdx.x;
    if (t >= NPAIR) return;
    int b = t >> 12;
    int i = (t >> 6) & 63;
    int j = t & 63;
    const float* pi = pos + (b*NN+i)*3;
    const float* pj = pos + (b*NN+j)*3;
    float dx = pi[0]-pj[0], dy = pi[1]-pj[1], dz = pi[2]-pj[2];
    float r = sqrtf(dx*dx + dy*dy + dz*dz + 1e-12f);
    float inv = 1.0f / r;
    float x = dx*inv, y = dy*inv, z = dz*inv;

    float cut = 0.0f;
    if (i != j && r > 1e-4f && r < 5.0f)
        cut = 1.0f / (1.0f + __expf((r - 3.0f) * 2.0f));
    g_cut[t] = cut;

    float xx = x*x, yy = y*y, zz = z*z;
    float4 s0 = make_float4(1.0f, x, y, z);
    float4 s1 = make_float4(x*y, y*z, 3.0f*zz - 1.0f, x*z);
    float4 s2 = make_float4(xx - yy,
                            y*(3.0f*xx - yy),
                            x*y*z,
                            y*(5.0f*zz - 1.0f));
    float4 s3 = make_float4(z*(5.0f*zz - 3.0f),
                            x*(5.0f*zz - 1.0f),
                            z*(xx - yy),
                            x*(xx - 3.0f*yy));
    float4* o = (float4*)(g_sph + t*16);
    o[0] = s0; o[1] = s1; o[2] = s2; o[3] = s3;

    // gaussian radial basis: exp(-36*(r - k*5/59)^2), k=0..59
    const float dc = 5.0f / 59.0f;
    float4* ob = (float4*)(g_basis + t*NB);
    #pragma unroll
    for (int kq = 0; kq < 15; ++kq) {
        float d0 = r - (float)(4*kq + 0) * dc;
        float d1 = r - (float)(4*kq + 1) * dc;
        float d2 = r - (float)(4*kq + 2) * dc;
        float d3 = r - (float)(4*kq + 3) * dc;
        float4 v;
        v.x = __expf(-36.0f * d0*d0);
        v.y = __expf(-36.0f * d1*d1);
        v.z = __expf(-36.0f * d2*d2);
        v.w = __expf(-36.0f * d3*d3);
        ob[kq] = v;
    }
}

// ---------------- input featurization: a0 = scalars_in @ W_in + b_in ----------------
__global__ void k_a0(const float* __restrict__ oh, const int* __restrict__ charges,
                     const float* __restrict__ W_in, const float* __restrict__ b_in) {
    int t = blockIdx.x*256 + threadIdx.x;
    if (t >= BB*NN*CC) return;
    int c = t & 31;
    int n = t >> 5;
    float ch = (float)charges[n] * (1.0f/9.0f);
    float p1 = ch, p2 = ch*ch;
    float acc = b_in[c];
    #pragma unroll
    for (int s = 0; s < 5; ++s) {
        float o = oh[n*5 + s];
        acc += o * (        W_in[(s*3+0)*CC + c]
                    + p1 *  W_in[(s*3+1)*CC + c]
                    + p2 *  W_in[(s*3+2)*CC + c]);
    }
    g_a[0][t] = acc;
    g_rep[0][(n*7 + 0)*CC + c] = acc;   // atom_reps[0][...,0] initial
    if (c == 0) g_part[n] = 0.0f;
}

// ---------------- one full Cormorant level, fused edge+aggregate ----------------
__global__ void __launch_bounds__(256) k_level(int lvl,
    const float* __restrict__ W_rad,  const float* __restrict__ W_edge,
    const float* __restrict__ W_agg,  const float* __restrict__ W_self,
    const float* __restrict__ W_top)
{
    __shared__ float sa[NN*CC];        // a[b,j,c] for all j           (8 KB)
    __shared__ float scut[NN];
    __shared__ float ssph[NN*16];      //                              (4 KB)
    __shared__ float sbasis[NN*NB];    //                              (15 KB)
    __shared__ float sWrad[NB*CC];     //                              (7.7 KB)
    __shared__ float sWE[CC*CC];       // W_edge during j-loop; reused for sred/srold/srnew
    __shared__ float ssij[8*CC];       // per-warp s_ij
    __shared__ float smsg[8*7*CC];     // per-warp msg partials        (7 KB)

    const float* acur  = g_a[lvl & 1];
    float*       anext = g_a[(lvl + 1) & 1];

    int blk = blockIdx.x;
    int b = blk >> 6, i = blk & 63;
    int tid = threadIdx.x, w = tid >> 5, lane = tid & 31;
    int pbase = (b*NN + i)*NN;

    // block-wide loads
    for (int idx = tid; idx < NN*CC/4; idx += 256)
        ((float4*)sa)[idx] = ((const float4*)(acur + b*NN*CC))[idx];
    for (int idx = tid; idx < NN/4; idx += 256)
        ((float4*)scut)[idx] = ((const float4*)(g_cut + pbase))[idx];
    for (int idx = tid; idx < NN*16/4; idx += 256)
        ((float4*)ssph)[idx] = ((const float4*)(g_sph + pbase*16))[idx];
    for (int idx = tid; idx < NN*NB/4; idx += 256)
        ((float4*)sbasis)[idx] = ((const float4*)(g_basis + pbase*NB))[idx];

    float part = 0.0f;

    for (int l = 0; l <= 3; ++l) {
        int M = 2*l + 1;
        __syncthreads();   // previous iteration done with all smem
        // stage level/l weights
        const float* wr = W_rad  + (lvl*4 + l)*NB*CC;
        for (int idx = tid; idx < NB*CC; idx += 256) sWrad[idx] = wr[idx];
        const float* we = W_edge + (lvl*4 + l)*CC*CC;
        for (int idx = tid; idx < CC*CC; idx += 256) sWE[idx] = we[idx];
        __syncthreads();

        float accm[7];
        #pragma unroll
        for (int m = 0; m < 7; ++m) accm[m] = 0.0f;
        int sphoff = l*l;                       // 0,1,4,9
        float* ge = g_edge[l] + pbase*CC;
        float ai = sa[i*CC + lane];

        for (int j = w; j < NN; j += 8) {
            ssij[w*CC + lane] = ai * sa[j*CC + lane];
            __syncwarp();
            float racc = 0.0f;
            #pragma unroll
            for (int k = 0; k < NB; ++k)
                racc += sbasis[j*NB + k] * sWrad[k*CC + lane];
            float eacc = 0.0f;
            #pragma unroll
            for (int d = 0; d < CC; ++d)
                eacc += ssij[w*CC + d] * sWE[d*CC + lane];
            if (lvl > 0) eacc += ge[j*CC + lane];
            float edge = scut[j] * racc * eacc;
            ge[j*CC + lane] = edge;
            #pragma unroll
            for (int m = 0; m < 7; ++m)
                if (m < M) accm[m] += edge * ssph[j*16 + sphoff + m];
            __syncwarp();
        }
        #pragma unroll
        for (int m = 0; m < 7; ++m)
            if (m < M) smsg[(w*7 + m)*CC + lane] = accm[m];
        __syncthreads();   // j-loop done -> sWE reusable

        float* sred  = sWE;             // M*32 <= 224 floats
        float* srold = sWE + 224;
        float* srnew = sWE + 448;       // 672 <= 1024 OK
        bool has_self = (lvl > 0) || (l == 0);

        if (tid < M*CC) {
            int m = tid >> 5, c = tid & 31;
            float s = 0.0f;
            #pragma unroll
            for (int ww = 0; ww < 8; ++ww) s += smsg[(ww*7 + m)*CC + c];
            sred[m*CC + c] = s;
            if (has_self)
                srold[m*CC + c] = g_rep[l][((b*NN + i)*7 + m)*CC + c];
        }
        __syncthreads();

        if (tid < M*CC) {
            int m = tid >> 5, d = tid & 31;
            const float* wa  = W_agg  + (lvl*4 + l)*CC*CC;
            const float* wsf = W_self + (lvl*4 + l)*CC*CC;
            float r = 0.0f;
            #pragma unroll
            for (int c2 = 0; c2 < CC; ++c2)
                r += sred[m*CC + c2] * wa[c2*CC + d];
            if (has_self) {
                #pragma unroll
                for (int c2 = 0; c2 < CC; ++c2)
                    r += srold[m*CC + c2] * wsf[c2*CC + d];
            }
            srnew[m*CC + d] = r;
            g_rep[l][((b*NN + i)*7 + m)*CC + d] = r;
            if (l == 0) anext[(b*NN + i)*CC + d] = r;
        }
        __syncthreads();

        if (tid < CC) {   // features + head dot for this (lvl,l)
            float f;
            if (l == 0) {
                f = srnew[tid];
            } else {
                float s2 = 0.0f;
                for (int m = 0; m < M; ++m) { float v = srnew[m*CC + tid]; s2 += v*v; }
                f = sqrtf(s2 + 1e-12f);
            }
            part += f * W_top[(lvl*4 + l)*CC + tid];
        }
    }

    __syncthreads();
    if (tid < 32) {
        #pragma unroll
        for (int off = 16; off; off >>= 1)
            part += __shfl_down_sync(0xffffffffu, part, off);
        if (tid == 0) g_part[b*NN + i] += part;
    }
}

// ---------------- output: pooled @ W_top (already dotted) + b_top ----------------
__global__ void k_out(float* __restrict__ out, const float* __restrict__ b_top) {
    __shared__ float s[64];
    int b = blockIdx.x, t = threadIdx.x;
    s[t] = g_part[b*NN + t];
    __syncthreads();
    #pragma unroll
    for (int off = 32; off; off >>= 1) {
        if (t < off) s[t] += s[t + off];
        __syncthreads();
    }
    if (t == 0) out[b] = s[0] + b_top[0];
}

// ---------------- launch ----------------
extern "C" void kernel_launch(void* const* d_in, const int* in_sizes, int n_in,
                              void* d_out, int out_size) {
    const float* pos     = (const float*)d_in[0];
    const float* oh      = (const float*)d_in[1];
    const int*   charges = (const int*)  d_in[2];
    // d_in[3]=atom_mask (all true), d_in[4]=edge_mask (~eye): reproduced analytically
    const float* W_in    = (const float*)d_in[5];
    const float* b_in    = (const float*)d_in[6];
    const float* W_rad   = (const float*)d_in[7];
    const float* W_edge  = (const float*)d_in[8];
    const float* W_agg   = (const float*)d_in[9];
    const float* W_self  = (const float*)d_in[10];
    const float* W_top   = (const float*)d_in[11];
    const float* b_top   = (const float*)d_in[12];

    k_geom<<<NPAIR/256, 256>>>(pos);
    k_a0<<<(BB*NN*CC)/256, 256>>>(oh, charges, W_in, b_in);
    for (int lvl = 0; lvl < NLVL; ++lvl)
        k_level<<<BB*NN, 256>>>(lvl, W_rad, W_edge, W_agg, W_self, W_top);
    k_out<<<BB, 64>>>((float*)d_out, b_top);
}

// round 2
// speedup vs baseline: 2.0718x; 2.0718x over previous
#include <cuda_runtime.h>

#define BB 16
#define NN 64
#define CC 32
#define NLVL 4
#define NB 60
#define NE 4096                 // radial table resolution over [0, 5]
#define NPAIR (BB*NN*NN)        // 65536

// ---------------- device scratch (static; no allocs) ----------------
__device__ float g_a[2][BB*NN*CC];            // ping-pong scalar reps
__device__ float g_rep[4][BB*NN*7*CC];        // [l][atom][m][c]
__device__ float g_edge[4][NPAIR*CC];         // [l][pair][c]
__device__ float g_cut[NPAIR];
__device__ float g_sph[NPAIR*16];             // 1+3+5+7 packed per pair
__device__ int   g_e0[NPAIR];
__device__ float g_frac[NPAIR];
__device__ float g_part[BB*NN];
__device__ float g_bas[(NE+1)*NB];            // basis values per table row
__device__ float g_tab[(NE+1)*512];           // rad table: [e][(lvl*4+l)*32+c]

// ---------------- basis table rows ----------------
__global__ void k_bas() {
    int t = blockIdx.x*256 + threadIdx.x;
    if (t >= (NE+1)*NB) return;
    int e = t / NB, k = t - e*NB;
    float r = (float)e * (5.0f/NE);
    float d = r - (float)k * (5.0f/59.0f);
    g_bas[t] = expf(-36.0f * d * d);
}

// ---------------- rad table: g_tab[e][s*32+c] = sum_k bas[e][k] * W_rad[s][k][c]
__global__ void __launch_bounds__(256) k_table(const float* __restrict__ W_rad) {
    __shared__ float sW[NB*CC];     // 7.7 KB
    __shared__ float sb[64*NB];     // 15.4 KB
    int s   = blockIdx.y;           // 0..15 -> (lvl,l)
    int e0b = blockIdx.x * 64;
    int tid = threadIdx.x;
    const float* wr = W_rad + s*NB*CC;
    for (int idx = tid; idx < NB*CC; idx += 256) sW[idx] = wr[idx];
    int nmax = (NE+1) - e0b; if (nmax > 64) nmax = 64;
    for (int idx = tid; idx < nmax*NB; idx += 256) sb[idx] = g_bas[e0b*NB + idx];
    __syncthreads();
    int c = tid & 31, eg = tid >> 5;   // warp eg handles e rows eg*8..eg*8+7
    float acc[8];
    #pragma unroll
    for (int t = 0; t < 8; ++t) acc[t] = 0.0f;
    for (int k = 0; k < NB; ++k) {
        float wv = sW[k*CC + c];
        #pragma unroll
        for (int t = 0; t < 8; ++t)
            acc[t] = fmaf(sb[(eg*8 + t)*NB + k], wv, acc[t]);
    }
    #pragma unroll
    for (int t = 0; t < 8; ++t) {
        int e = e0b + eg*8 + t;
        if (e <= NE) g_tab[e*512 + s*32 + c] = acc[t];
    }
}

// ---------------- geometry: cutoff, sph, table index ----------------
__global__ void k_geom(const float* __restrict__ pos) {
    int t = blockIdx.x*256 + threadIdx.x;
    if (t >= NPAIR) return;
    int b = t >> 12, i = (t >> 6) & 63, j = t & 63;
    const float* pi = pos + (b*NN+i)*3;
    const float* pj = pos + (b*NN+j)*3;
    float dx = pi[0]-pj[0], dy = pi[1]-pj[1], dz = pi[2]-pj[2];
    float r = sqrtf(dx*dx + dy*dy + dz*dz + 1e-12f);
    float inv = 1.0f / r;
    float x = dx*inv, y = dy*inv, z = dz*inv;

    float cut = 0.0f;
    if (i != j && r > 1e-4f && r < 5.0f)
        cut = 1.0f / (1.0f + __expf((r - 3.0f) * 2.0f));
    g_cut[t] = cut;

    float fidx = r * ((float)NE / 5.0f);
    int e0 = (int)fidx;
    if (e0 > NE-1) e0 = NE-1;
    float fr = fidx - (float)e0;
    if (fr > 1.0f) fr = 1.0f;
    g_e0[t] = e0;
    g_frac[t] = fr;

    float xx = x*x, yy = y*y, zz = z*z;
    float4 s0 = make_float4(1.0f, x, y, z);
    float4 s1 = make_float4(x*y, y*z, 3.0f*zz - 1.0f, x*z);
    float4 s2 = make_float4(xx - yy, y*(3.0f*xx - yy), x*y*z, y*(5.0f*zz - 1.0f));
    float4 s3 = make_float4(z*(5.0f*zz - 3.0f), x*(5.0f*zz - 1.0f),
                            z*(xx - yy), x*(xx - 3.0f*yy));
    float4* o = (float4*)(g_sph + t*16);
    o[0] = s0; o[1] = s1; o[2] = s2; o[3] = s3;
}

// ---------------- input featurization ----------------
__global__ void k_a0(const float* __restrict__ oh, const int* __restrict__ charges,
                     const float* __restrict__ W_in, const float* __restrict__ b_in) {
    int t = blockIdx.x*256 + threadIdx.x;
    if (t >= BB*NN*CC) return;
    int c = t & 31, n = t >> 5;
    float ch = (float)charges[n] * (1.0f/9.0f);
    float p1 = ch, p2 = ch*ch;
    float acc = b_in[c];
    #pragma unroll
    for (int s = 0; s < 5; ++s) {
        float o = oh[n*5 + s];
        acc += o * (W_in[(s*3+0)*CC + c] + p1*W_in[(s*3+1)*CC + c] + p2*W_in[(s*3+2)*CC + c]);
    }
    g_a[0][t] = acc;
    g_rep[0][(n*7 + 0)*CC + c] = acc;
    if (c == 0) g_part[n] = 0.0f;
}

// ---------------- one full Cormorant level ----------------
__global__ void __launch_bounds__(256) k_level(int lvl,
    const float* __restrict__ W_edge, const float* __restrict__ W_agg,
    const float* __restrict__ W_self, const float* __restrict__ W_top)
{
    __shared__ float sa[NN*CC];        // 8 KB
    __shared__ float scut[NN];
    __shared__ float sfrac[NN];
    __shared__ int   se0[NN];
    __shared__ float ssph[NN*16];      // 4 KB
    __shared__ float sWE[CC*CC];       // 4 KB; reused by epilogue
    __shared__ float smsg[8*7*CC];     // 7 KB

    const float* acur  = g_a[lvl & 1];
    float*       anext = g_a[(lvl + 1) & 1];

    int blk = blockIdx.x;
    int b = blk >> 6, i = blk & 63;
    int tid = threadIdx.x, w = tid >> 5, lane = tid & 31;
    int pbase = (b*NN + i)*NN;

    for (int idx = tid; idx < NN*CC/4; idx += 256)
        ((float4*)sa)[idx] = ((const float4*)(acur + b*NN*CC))[idx];
    for (int idx = tid; idx < NN/4; idx += 256) {
        ((float4*)scut)[idx]  = ((const float4*)(g_cut  + pbase))[idx];
        ((float4*)sfrac)[idx] = ((const float4*)(g_frac + pbase))[idx];
        ((int4*)se0)[idx]     = ((const int4*)  (g_e0   + pbase))[idx];
    }
    for (int idx = tid; idx < NN*16/4; idx += 256)
        ((float4*)ssph)[idx] = ((const float4*)(g_sph + pbase*16))[idx];

    float part = 0.0f;

    #pragma unroll
    for (int l = 0; l <= 3; ++l) {
        const int M = 2*l + 1;
        __syncthreads();
        const float* we = W_edge + (lvl*4 + l)*CC*CC;
        for (int idx = tid; idx < CC*CC; idx += 256) sWE[idx] = we[idx];
        __syncthreads();

        // fold a_i into the weight column: vreg[d] = a_i[d] * W[d][lane]
        float vreg[32];
        #pragma unroll
        for (int d = 0; d < 32; ++d)
            vreg[d] = sa[i*CC + d] * sWE[d*CC + lane];

        float accm[7];
        #pragma unroll
        for (int m = 0; m < 7; ++m) accm[m] = 0.0f;
        float* ge = g_edge[l] + pbase*CC;
        const float* tabl = g_tab + (lvl*4 + l)*32 + lane;

        for (int jt = 0; jt < 8; ++jt) {
            int j = w + jt*8;
            const float4* aj4 = (const float4*)(sa + j*CC);
            float ea0 = 0.f, ea1 = 0.f, ea2 = 0.f, ea3 = 0.f;
            #pragma unroll
            for (int q = 0; q < 8; ++q) {
                float4 s4 = aj4[q];
                ea0 = fmaf(s4.x, vreg[4*q+0], ea0);
                ea1 = fmaf(s4.y, vreg[4*q+1], ea1);
                ea2 = fmaf(s4.z, vreg[4*q+2], ea2);
                ea3 = fmaf(s4.w, vreg[4*q+3], ea3);
            }
            float eacc = (ea0 + ea1) + (ea2 + ea3);
            if (lvl > 0) eacc += ge[j*CC + lane];
            const float* tp = tabl + se0[j]*512;
            float t0 = tp[0], t1 = tp[512];
            float rad = fmaf(sfrac[j], t1 - t0, t0);
            float edge = scut[j] * rad * eacc;
            ge[j*CC + lane] = edge;

            if (l == 0) {
                accm[0] += edge;
            } else if (l == 1) {
                float4 sp = *(const float4*)(ssph + j*16);
                accm[0] = fmaf(edge, sp.y, accm[0]);
                accm[1] = fmaf(edge, sp.z, accm[1]);
                accm[2] = fmaf(edge, sp.w, accm[2]);
            } else if (l == 2) {
                float4 sp = *(const float4*)(ssph + j*16 + 4);
                float s8 = ssph[j*16 + 8];
                accm[0] = fmaf(edge, sp.x, accm[0]);
                accm[1] = fmaf(edge, sp.y, accm[1]);
                accm[2] = fmaf(edge, sp.z, accm[2]);
                accm[3] = fmaf(edge, sp.w, accm[3]);
                accm[4] = fmaf(edge, s8,   accm[4]);
            } else {
                float4 spa = *(const float4*)(ssph + j*16 + 8);
                float4 spb = *(const float4*)(ssph + j*16 + 12);
                accm[0] = fmaf(edge, spa.y, accm[0]);
                accm[1] = fmaf(edge, spa.z, accm[1]);
                accm[2] = fmaf(edge, spa.w, accm[2]);
                accm[3] = fmaf(edge, spb.x, accm[3]);
                accm[4] = fmaf(edge, spb.y, accm[4]);
                accm[5] = fmaf(edge, spb.z, accm[5]);
                accm[6] = fmaf(edge, spb.w, accm[6]);
            }
        }
        #pragma unroll
        for (int m = 0; m < 7; ++m)
            if (m < M) smsg[(w*7 + m)*CC + lane] = accm[m];
        __syncthreads();

        float* sred  = sWE;
        float* srold = sWE + 224;
        float* srnew = sWE + 448;
        bool has_self = (lvl > 0) || (l == 0);

        if (tid < M*CC) {
            int m = tid >> 5, c = tid & 31;
            float s = 0.0f;
            #pragma unroll
            for (int ww = 0; ww < 8; ++ww) s += smsg[(ww*7 + m)*CC + c];
            sred[m*CC + c] = s;
            if (has_self)
                srold[m*CC + c] = g_rep[l][((b*NN + i)*7 + m)*CC + c];
        }
        __syncthreads();

        if (tid < M*CC) {
            int m = tid >> 5, d = tid & 31;
            const float* wa  = W_agg  + (lvl*4 + l)*CC*CC;
            const float* wsf = W_self + (lvl*4 + l)*CC*CC;
            float r = 0.0f;
            #pragma unroll
            for (int c2 = 0; c2 < CC; ++c2)
                r = fmaf(sred[m*CC + c2], wa[c2*CC + d], r);
            if (has_self) {
                #pragma unroll
                for (int c2 = 0; c2 < CC; ++c2)
                    r = fmaf(srold[m*CC + c2], wsf[c2*CC + d], r);
            }
            srnew[m*CC + d] = r;
            g_rep[l][((b*NN + i)*7 + m)*CC + d] = r;
            if (l == 0) anext[(b*NN + i)*CC + d] = r;
        }
        __syncthreads();

        if (tid < CC) {
            float f;
            if (l == 0) {
                f = srnew[tid];
            } else {
                float s2 = 0.0f;
                for (int m = 0; m < M; ++m) { float v = srnew[m*CC + tid]; s2 += v*v; }
                f = sqrtf(s2 + 1e-12f);
            }
            part = fmaf(f, W_top[(lvl*4 + l)*CC + tid], part);
        }
    }

    __syncthreads();
    if (tid < 32) {
        #pragma unroll
        for (int off = 16; off; off >>= 1)
            part += __shfl_down_sync(0xffffffffu, part, off);
        if (tid == 0) g_part[b*NN + i] += part;
    }
}

// ---------------- output ----------------
__global__ void k_out(float* __restrict__ out, const float* __restrict__ b_top) {
    __shared__ float s[64];
    int b = blockIdx.x, t = threadIdx.x;
    s[t] = g_part[b*NN + t];
    __syncthreads();
    #pragma unroll
    for (int off = 32; off; off >>= 1) {
        if (t < off) s[t] += s[t + off];
        __syncthreads();
    }
    if (t == 0) out[b] = s[0] + b_top[0];
}

// ---------------- launch ----------------
extern "C" void kernel_launch(void* const* d_in, const int* in_sizes, int n_in,
                              void* d_out, int out_size) {
    const float* pos     = (const float*)d_in[0];
    const float* oh      = (const float*)d_in[1];
    const int*   charges = (const int*)  d_in[2];
    const float* W_in    = (const float*)d_in[5];
    const float* b_in    = (const float*)d_in[6];
    const float* W_rad   = (const float*)d_in[7];
    const float* W_edge  = (const float*)d_in[8];
    const float* W_agg   = (const float*)d_in[9];
    const float* W_self  = (const float*)d_in[10];
    const float* W_top   = (const float*)d_in[11];
    const float* b_top   = (const float*)d_in[12];

    k_bas<<<((NE+1)*NB + 255)/256, 256>>>();
    k_table<<<dim3((NE+64)/64, 16), 256>>>(W_rad);
    k_geom<<<NPAIR/256, 256>>>(pos);
    k_a0<<<(BB*NN*CC)/256, 256>>>(oh, charges, W_in, b_in);
    for (int lvl = 0; lvl < NLVL; ++lvl)
        k_level<<<BB*NN, 256>>>(lvl, W_edge, W_agg, W_self, W_top);
    k_out<<<BB, 64>>>((float*)d_out, b_top);
}